// round 13
// baseline (speedup 1.0000x reference)
#include <cuda_runtime.h>
#include <cuda_fp16.h>

#define NN 50000
#define NE 800000
#define IND 128
#define HID 64
#define HEADS 4
#define C1 256            // HEADS*HID
#define EDIM 16

// ---------------- scratch (device globals) ----------------
__device__ uint4    g_h1h[NN * 32];         // [N,256] h1, fp16
__device__ __half2  g_out1h[NN * 128];      // [N,256] relu(agg1+b1), fp16
__device__ __half2  g_h2h[NN * 32];         // [N,64]  h2, fp16
__device__ __half   g_w1t[C1 * IND];        // W1^T fp16 [256 n][128 k]
__device__ __half   g_w2t[HID * C1];        // W2^T fp16 [64 n][256 k]
__device__ float4   g_scr1[NE];             // exp(logits) 4 heads, AT CSR POS
__device__ int2     g_misc[NE];             // (src, ae2-bits), AT CSR POS
__device__ float4   g_asrc1[NN], g_adst1[NN];
__device__ float    g_asrc2[NN], g_adst2[NN];
__device__ float    g_v1[EDIM * HEADS];
__device__ float    g_v2[EDIM];
__device__ unsigned g_deg[NN];
__device__ unsigned g_cnt[NN];
__device__ unsigned g_ptr[NN + 1];

// ---------------- helpers ----------------
__device__ __forceinline__ float lrelu(float x) { return x > 0.f ? x : 0.2f * x; }
__device__ __forceinline__ float2 h2f(unsigned u) {
    return __half22float2(*reinterpret_cast<__half2*>(&u));
}
__device__ __forceinline__ void mma16816(float* c, const unsigned* a,
                                         unsigned b0, unsigned b1) {
    asm volatile(
        "mma.sync.aligned.m16n8k16.row.col.f32.f16.f16.f32 "
        "{%0,%1,%2,%3}, {%4,%5,%6,%7}, {%8,%9}, {%0,%1,%2,%3};"
        : "+f"(c[0]), "+f"(c[1]), "+f"(c[2]), "+f"(c[3])
        : "r"(a[0]), "r"(a[1]), "r"(a[2]), "r"(a[3]), "r"(b0), "r"(b1));
}
__device__ __forceinline__ void ldsm4(unsigned* r, unsigned addr) {
    asm volatile("ldmatrix.sync.aligned.m8n8.x4.shared.b16 {%0,%1,%2,%3}, [%4];"
                 : "=r"(r[0]), "=r"(r[1]), "=r"(r[2]), "=r"(r[3]) : "r"(addr));
}

// ---------------- kernels ----------------
// main stream: W1^T transpose + zero attention accumulators (gemm1's deps only)
__global__ __launch_bounds__(256) void k_initA(const float* __restrict__ W1) {
    int i = blockIdx.x * blockDim.x + threadIdx.x;
    if (i < NN) {
        float4 z = make_float4(0.f, 0.f, 0.f, 0.f);
        g_asrc1[i] = z; g_adst1[i] = z;
        g_asrc2[i] = 0.f; g_adst2[i] = 0.f;
    }
    if (i < C1 * IND) {
        int n = i >> 7, k = i & 127;
        g_w1t[i] = __float2half_rn(W1[k * C1 + n]);
    }
}

// stream B: zero degree counters
__global__ __launch_bounds__(256) void k_initdeg() {
    int i = blockIdx.x * blockDim.x + threadIdx.x;
    if (i < NN) g_deg[i] = 0u;
}

// stream B: W2^T + collapsed edge-attention vectors (warp per output)
__global__ __launch_bounds__(256) void k_initB(const float* __restrict__ We1,
                                               const float* __restrict__ ae1,
                                               const float* __restrict__ We2,
                                               const float* __restrict__ ae2,
                                               const float* __restrict__ W2) {
    int i = blockIdx.x * blockDim.x + threadIdx.x;
    if (i < HID * C1) {
        int n = i >> 8, k = i & 255;
        g_w2t[i] = __float2half_rn(W2[k * HID + n]);
    }
    int gw = i >> 5, lane = i & 31;
    if (gw < EDIM * HEADS) {
        int d = gw >> 2, h = gw & 3;
        float s = We1[d * C1 + h * HID + lane]        * ae1[h * HID + lane]
                + We1[d * C1 + h * HID + lane + 32]   * ae1[h * HID + lane + 32];
#pragma unroll
        for (int o = 16; o >= 1; o >>= 1) s += __shfl_xor_sync(0xFFFFFFFFu, s, o);
        if (lane == 0) g_v1[gw] = s;
    } else if (gw < EDIM * HEADS + EDIM) {
        int t = gw - EDIM * HEADS;
        float s = We2[t * HID + lane] * ae2[lane]
                + We2[t * HID + lane + 32] * ae2[lane + 32];
#pragma unroll
        for (int o = 16; o >= 1; o >>= 1) s += __shfl_xor_sync(0xFFFFFFFFu, s, o);
        if (lane == 0) g_v2[t] = s;
    }
}

__global__ __launch_bounds__(256) void k_hist(const int* __restrict__ ei) {
    int e = blockIdx.x * blockDim.x + threadIdx.x;
    if (e < NE) atomicAdd(&g_deg[ei[NE + e]], 1u);
}

// single-block exclusive scan of degrees -> g_ptr, g_cnt
__global__ __launch_bounds__(1024) void k_scan() {
    __shared__ unsigned wsum[32];
    const int T = 1024;
    int t = threadIdx.x;
    int per = (NN + T - 1) / T;
    int b = t * per, e = min(b + per, NN);
    unsigned s = 0;
    for (int i = b; i < e; i++) s += g_deg[i];
    unsigned lane = t & 31, wid = t >> 5;
    unsigned incl = s;
#pragma unroll
    for (int o = 1; o < 32; o <<= 1) {
        unsigned u = __shfl_up_sync(0xFFFFFFFFu, incl, o);
        if (lane >= (unsigned)o) incl += u;
    }
    if (lane == 31) wsum[wid] = incl;
    __syncthreads();
    if (wid == 0) {
        unsigned v = wsum[lane];
        unsigned vi = v;
#pragma unroll
        for (int o = 1; o < 32; o <<= 1) {
            unsigned u = __shfl_up_sync(0xFFFFFFFFu, vi, o);
            if (lane >= (unsigned)o) vi += u;
        }
        wsum[lane] = vi - v;
    }
    __syncthreads();
    unsigned run = incl - s + wsum[wid];
    for (int i = b; i < e; i++) {
        unsigned d = g_deg[i];
        g_ptr[i] = run;
        g_cnt[i] = run;
        run += d;
    }
    if (t == T - 1) g_ptr[NN] = NE;
}

// ---- h1 = x @ W1 via HMMA+LDSM, att1 dots fused in epilogue ----
#define XS1_STRIDE 136
#define WS1_STRIDE 136
#define G1_SMEM ((64 * XS1_STRIDE + 128 * WS1_STRIDE) * 2)

__global__ __launch_bounds__(256) void k_gemm1(const float* __restrict__ x,
                                               const float* __restrict__ as1,
                                               const float* __restrict__ ad1) {
    extern __shared__ __half sm1[];
    __half* xs = sm1;                     // [64 m][136 k]
    __half* ws = sm1 + 64 * XS1_STRIDE;   // [128 n][136 k]
    int t = threadIdx.x;
    int node0 = blockIdx.x * 64;
    int ncol0 = blockIdx.y * 128;
#pragma unroll
    for (int i = 0; i < 8; i++) {
        int j = i * 256 + t;
        int m = j >> 5, kq = j & 31;
        float4 v = make_float4(0.f, 0.f, 0.f, 0.f);
        if (node0 + m < NN) v = ((const float4*)x)[(size_t)(node0 + m) * 32 + kq];
        *(__half2*)&xs[m * XS1_STRIDE + kq * 4]     = __floats2half2_rn(v.x, v.y);
        *(__half2*)&xs[m * XS1_STRIDE + kq * 4 + 2] = __floats2half2_rn(v.z, v.w);
    }
#pragma unroll
    for (int i = 0; i < 8; i++) {
        int j = i * 256 + t;
        int n = j >> 4, q = j & 15;
        uint4 v = ((const uint4*)(g_w1t + (size_t)(ncol0 + n) * IND))[q];
        *(uint4*)&ws[n * WS1_STRIDE + q * 8] = v;
    }
    __syncthreads();
    int warp = t >> 5, lane = t & 31;
    int wm = warp & 1, wn = warp >> 1;
    int m_base = wm * 32, n_base = wn * 32;
    unsigned xs_sa = (unsigned)__cvta_generic_to_shared(xs);
    unsigned ws_sa = (unsigned)__cvta_generic_to_shared(ws);
    unsigned aA = xs_sa + ((m_base + ((lane >> 3) & 1) * 8 + (lane & 7)) * XS1_STRIDE
                           + (lane >> 4) * 8) * 2;
    unsigned aB = ws_sa + ((n_base + (lane >> 4) * 8 + (lane & 7)) * WS1_STRIDE
                           + ((lane >> 3) & 1) * 8) * 2;
    float c[2][4][4];
#pragma unroll
    for (int i = 0; i < 2; i++)
#pragma unroll
        for (int j = 0; j < 4; j++)
#pragma unroll
            for (int q = 0; q < 4; q++) c[i][j][q] = 0.f;
#pragma unroll
    for (int k0 = 0; k0 < IND; k0 += 16) {
        unsigned a0[4], a1[4], b0[4], b1[4];
        ldsm4(a0, aA + k0 * 2);
        ldsm4(a1, aA + (16 * XS1_STRIDE + k0) * 2);
        ldsm4(b0, aB + k0 * 2);
        ldsm4(b1, aB + (16 * WS1_STRIDE + k0) * 2);
        mma16816(c[0][0], a0, b0[0], b0[1]);
        mma16816(c[0][1], a0, b0[2], b0[3]);
        mma16816(c[0][2], a0, b1[0], b1[1]);
        mma16816(c[0][3], a0, b1[2], b1[3]);
        mma16816(c[1][0], a1, b0[0], b0[1]);
        mma16816(c[1][1], a1, b0[2], b0[3]);
        mma16816(c[1][2], a1, b1[0], b1[1]);
        mma16816(c[1][3], a1, b1[2], b1[3]);
    }
    int r = lane >> 2, kp = (lane & 3) * 2;
    __half* h1 = (__half*)g_h1h;
#pragma unroll
    for (int mt = 0; mt < 2; mt++) {
#pragma unroll
        for (int nt = 0; nt < 4; nt++) {
            int row = node0 + m_base + mt * 16 + r;
            int col = ncol0 + n_base + nt * 8 + kp;
            if (row < NN)
                *(__half2*)&h1[(size_t)row * C1 + col] =
                    __floats2half2_rn(c[mt][nt][0], c[mt][nt][1]);
            if (row + 8 < NN)
                *(__half2*)&h1[(size_t)(row + 8) * C1 + col] =
                    __floats2half2_rn(c[mt][nt][2], c[mt][nt][3]);
        }
    }
    // fused attention dots: partial over this warp's 32 cols, quad-reduce, REDG
    float ps[2][2] = {{0.f, 0.f}, {0.f, 0.f}};
    float pd[2][2] = {{0.f, 0.f}, {0.f, 0.f}};
#pragma unroll
    for (int nt = 0; nt < 4; nt++) {
        int colg = ncol0 + n_base + nt * 8 + kp;
        float sa0 = as1[colg], sa1 = as1[colg + 1];
        float da0 = ad1[colg], da1 = ad1[colg + 1];
#pragma unroll
        for (int mt = 0; mt < 2; mt++) {
            ps[mt][0] += c[mt][nt][0] * sa0 + c[mt][nt][1] * sa1;
            pd[mt][0] += c[mt][nt][0] * da0 + c[mt][nt][1] * da1;
            ps[mt][1] += c[mt][nt][2] * sa0 + c[mt][nt][3] * sa1;
            pd[mt][1] += c[mt][nt][2] * da0 + c[mt][nt][3] * da1;
        }
    }
#pragma unroll
    for (int o = 1; o <= 2; o <<= 1) {
#pragma unroll
        for (int mt = 0; mt < 2; mt++)
#pragma unroll
            for (int rh = 0; rh < 2; rh++) {
                ps[mt][rh] += __shfl_xor_sync(0xFFFFFFFFu, ps[mt][rh], o);
                pd[mt][rh] += __shfl_xor_sync(0xFFFFFFFFu, pd[mt][rh], o);
            }
    }
    if ((lane & 3) == 0) {
        int head = (ncol0 + n_base) >> 6;
        float* s1f = (float*)g_asrc1;
        float* d1f = (float*)g_adst1;
#pragma unroll
        for (int mt = 0; mt < 2; mt++)
#pragma unroll
            for (int rh = 0; rh < 2; rh++) {
                int row = node0 + m_base + mt * 16 + rh * 8 + r;
                if (row < NN) {
                    atomicAdd(&s1f[row * 4 + head], ps[mt][rh]);
                    atomicAdd(&d1f[row * 4 + head], pd[mt][rh]);
                }
            }
    }
}

// per-edge logits + CSR scatter fused; 4 edges/thread for MLP
__global__ __launch_bounds__(256) void k_edge1(const int* __restrict__ ei,
                                               const float* __restrict__ eattr) {
    __shared__ float v1s[EDIM * HEADS];
    __shared__ float v2s[EDIM];
    if (threadIdx.x < EDIM * HEADS) v1s[threadIdx.x] = g_v1[threadIdx.x];
    if (threadIdx.x < EDIM)         v2s[threadIdx.x] = g_v2[threadIdx.x];
    __syncthreads();
    int base = blockIdx.x * blockDim.x + threadIdx.x;
    if (base >= NE / 4) return;
    int eidx[4] = {base, base + NE / 4, base + NE / 2, base + 3 * (NE / 4)};
    int s[4], d[4];
    float4 av[4], dv[4];
#pragma unroll
    for (int u = 0; u < 4; u++) {
        s[u] = ei[eidx[u]];
        d[u] = ei[NE + eidx[u]];
    }
#pragma unroll
    for (int u = 0; u < 4; u++) {
        av[u] = g_asrc1[s[u]];
        dv[u] = g_adst1[d[u]];
    }
#pragma unroll
    for (int u = 0; u < 4; u++) {
        const float4* ea = (const float4*)(eattr + (size_t)eidx[u] * EDIM);
        float ae[4] = {0.f, 0.f, 0.f, 0.f};
        float aev2 = 0.f;
#pragma unroll
        for (int j = 0; j < 4; j++) {
            float4 v = ea[j];
            float vals[4] = {v.x, v.y, v.z, v.w};
#pragma unroll
            for (int m = 0; m < 4; m++) {
                int dd = j * 4 + m;
                float ev = vals[m];
#pragma unroll
                for (int h = 0; h < 4; h++) ae[h] = fmaf(ev, v1s[dd * 4 + h], ae[h]);
                aev2 = fmaf(ev, v2s[dd], aev2);
            }
        }
        float4 ex;
        ex.x = __expf(lrelu(av[u].x + dv[u].x + ae[0]));
        ex.y = __expf(lrelu(av[u].y + dv[u].y + ae[1]));
        ex.z = __expf(lrelu(av[u].z + dv[u].z + ae[2]));
        ex.w = __expf(lrelu(av[u].w + dv[u].w + ae[3]));
        unsigned pos = atomicAdd(&g_cnt[d[u]], 1u);
        g_scr1[pos] = ex;
        g_misc[pos] = make_int2(s[u], __float_as_int(aev2));
    }
}

// layer-1 aggregation: warp per dst node, 4-wide unroll; bias+relu epilogue
__global__ __launch_bounds__(256) void k_agg1(const float* __restrict__ b1) {
    int w = (blockIdx.x * blockDim.x + threadIdx.x) >> 5;
    int lane = threadIdx.x & 31;
    if (w >= NN) return;
    unsigned beg = g_ptr[w], end = g_ptr[w + 1];
    int h = lane >> 3;
    const float* scr = (const float*)g_scr1;
    float a[8] = {0.f, 0.f, 0.f, 0.f, 0.f, 0.f, 0.f, 0.f};
    float ds = 0.f;
    unsigned j = beg;
    for (; j + 4 <= end; j += 4) {
        int s0 = g_misc[j].x, s1 = g_misc[j + 1].x;
        int s2 = g_misc[j + 2].x, s3 = g_misc[j + 3].x;
        float x0 = scr[(size_t)j * 4 + h];
        float x1 = scr[(size_t)(j + 1) * 4 + h];
        float x2 = scr[(size_t)(j + 2) * 4 + h];
        float x3 = scr[(size_t)(j + 3) * 4 + h];
        uint4 v0 = g_h1h[(size_t)s0 * 32 + lane];
        uint4 v1 = g_h1h[(size_t)s1 * 32 + lane];
        uint4 v2 = g_h1h[(size_t)s2 * 32 + lane];
        uint4 v3 = g_h1h[(size_t)s3 * 32 + lane];
        ds += (x0 + x1) + (x2 + x3);
        float2 f;
        f = h2f(v0.x); a[0] = fmaf(f.x, x0, a[0]); a[1] = fmaf(f.y, x0, a[1]);
        f = h2f(v0.y); a[2] = fmaf(f.x, x0, a[2]); a[3] = fmaf(f.y, x0, a[3]);
        f = h2f(v0.z); a[4] = fmaf(f.x, x0, a[4]); a[5] = fmaf(f.y, x0, a[5]);
        f = h2f(v0.w); a[6] = fmaf(f.x, x0, a[6]); a[7] = fmaf(f.y, x0, a[7]);
        f = h2f(v1.x); a[0] = fmaf(f.x, x1, a[0]); a[1] = fmaf(f.y, x1, a[1]);
        f = h2f(v1.y); a[2] = fmaf(f.x, x1, a[2]); a[3] = fmaf(f.y, x1, a[3]);
        f = h2f(v1.z); a[4] = fmaf(f.x, x1, a[4]); a[5] = fmaf(f.y, x1, a[5]);
        f = h2f(v1.w); a[6] = fmaf(f.x, x1, a[6]); a[7] = fmaf(f.y, x1, a[7]);
        f = h2f(v2.x); a[0] = fmaf(f.x, x2, a[0]); a[1] = fmaf(f.y, x2, a[1]);
        f = h2f(v2.y); a[2] = fmaf(f.x, x2, a[2]); a[3] = fmaf(f.y, x2, a[3]);
        f = h2f(v2.z); a[4] = fmaf(f.x, x2, a[4]); a[5] = fmaf(f.y, x2, a[5]);
        f = h2f(v2.w); a[6] = fmaf(f.x, x2, a[6]); a[7] = fmaf(f.y, x2, a[7]);
        f = h2f(v3.x); a[0] = fmaf(f.x, x3, a[0]); a[1] = fmaf(f.y, x3, a[1]);
        f = h2f(v3.y); a[2] = fmaf(f.x, x3, a[2]); a[3] = fmaf(f.y, x3, a[3]);
        f = h2f(v3.z); a[4] = fmaf(f.x, x3, a[4]); a[5] = fmaf(f.y, x3, a[5]);
        f = h2f(v3.w); a[6] = fmaf(f.x, x3, a[6]); a[7] = fmaf(f.y, x3, a[7]);
    }
    for (; j < end; j++) {
        int s0 = g_misc[j].x;
        float x0 = scr[(size_t)j * 4 + h];
        uint4 v0 = g_h1h[(size_t)s0 * 32 + lane];
        ds += x0;
        float2 f;
        f = h2f(v0.x); a[0] = fmaf(f.x, x0, a[0]); a[1] = fmaf(f.y, x0, a[1]);
        f = h2f(v0.y); a[2] = fmaf(f.x, x0, a[2]); a[3] = fmaf(f.y, x0, a[3]);
        f = h2f(v0.z); a[4] = fmaf(f.x, x0, a[4]); a[5] = fmaf(f.y, x0, a[5]);
        f = h2f(v0.w); a[6] = fmaf(f.x, x0, a[6]); a[7] = fmaf(f.y, x0, a[7]);
    }
    float inv = 1.f / (ds + 1e-16f);
    float4 b0 = ((const float4*)b1)[2 * lane];
    float4 b1v = ((const float4*)b1)[2 * lane + 1];
    __half2 r0 = __floats2half2_rn(fmaxf(a[0] * inv + b0.x, 0.f),
                                   fmaxf(a[1] * inv + b0.y, 0.f));
    __half2 r1 = __floats2half2_rn(fmaxf(a[2] * inv + b0.z, 0.f),
                                   fmaxf(a[3] * inv + b0.w, 0.f));
    __half2 r2 = __floats2half2_rn(fmaxf(a[4] * inv + b1v.x, 0.f),
                                   fmaxf(a[5] * inv + b1v.y, 0.f));
    __half2 r3 = __floats2half2_rn(fmaxf(a[6] * inv + b1v.z, 0.f),
                                   fmaxf(a[7] * inv + b1v.w, 0.f));
    uint4 pk;
    pk.x = *(unsigned*)&r0; pk.y = *(unsigned*)&r1;
    pk.z = *(unsigned*)&r2; pk.w = *(unsigned*)&r3;
    *reinterpret_cast<uint4*>(&g_out1h[(size_t)w * 128 + lane * 4]) = pk;
}

// ---- h2 = out1 @ W2 via HMMA+LDSM, att2 dots fused in epilogue ----
#define XS2_STRIDE 264
#define WS2_STRIDE 264
#define G2_SMEM ((64 * XS2_STRIDE + 64 * WS2_STRIDE) * 2)

__global__ __launch_bounds__(256) void k_gemm2(const float* __restrict__ as2,
                                               const float* __restrict__ ad2) {
    extern __shared__ __half sm2[];
    __half* xs = sm2;                     // [64 m][264 k]
    __half* ws = sm2 + 64 * XS2_STRIDE;   // [64 n][264 k]
    int t = threadIdx.x;
    int node0 = blockIdx.x * 64;
#pragma unroll
    for (int i = 0; i < 8; i++) {
        int j = i * 256 + t;
        int m = j >> 5, q = j & 31;
        uint4 v = make_uint4(0u, 0u, 0u, 0u);
        if (node0 + m < NN)
            v = ((const uint4*)g_out1h)[(size_t)(node0 + m) * 32 + q];
        *(uint4*)&xs[m * XS2_STRIDE + q * 8] = v;
    }
#pragma unroll
    for (int i = 0; i < 8; i++) {
        int j = i * 256 + t;
        int n = j >> 5, q = j & 31;
        uint4 v = ((const uint4*)(g_w2t + (size_t)n * C1))[q];
        *(uint4*)&ws[n * WS2_STRIDE + q * 8] = v;
    }
    __syncthreads();
    int warp = t >> 5, lane = t & 31;
    int wm = warp & 3, wn = warp >> 2;
    int m_base = wm * 16, n_base = wn * 32;
    unsigned xs_sa = (unsigned)__cvta_generic_to_shared(xs);
    unsigned ws_sa = (unsigned)__cvta_generic_to_shared(ws);
    unsigned aA = xs_sa + ((m_base + ((lane >> 3) & 1) * 8 + (lane & 7)) * XS2_STRIDE
                           + (lane >> 4) * 8) * 2;
    unsigned aB = ws_sa + ((n_base + (lane >> 4) * 8 + (lane & 7)) * WS2_STRIDE
                           + ((lane >> 3) & 1) * 8) * 2;
    float c[4][4];
#pragma unroll
    for (int j = 0; j < 4; j++)
#pragma unroll
        for (int q = 0; q < 4; q++) c[j][q] = 0.f;
#pragma unroll
    for (int k0 = 0; k0 < C1; k0 += 16) {
        unsigned a[4], b0[4], b1[4];
        ldsm4(a, aA + k0 * 2);
        ldsm4(b0, aB + k0 * 2);
        ldsm4(b1, aB + (16 * WS2_STRIDE + k0) * 2);
        mma16816(c[0], a, b0[0], b0[1]);
        mma16816(c[1], a, b0[2], b0[3]);
        mma16816(c[2], a, b1[0], b1[1]);
        mma16816(c[3], a, b1[2], b1[3]);
    }
    int r = lane >> 2, kp = (lane & 3) * 2;
    __half* h2 = (__half*)g_h2h;
#pragma unroll
    for (int nt = 0; nt < 4; nt++) {
        int row = node0 + m_base + r;
        int col = n_base + nt * 8 + kp;
        if (row < NN)
            *(__half2*)&h2[(size_t)row * HID + col] =
                __floats2half2_rn(c[nt][0], c[nt][1]);
        if (row + 8 < NN)
            *(__half2*)&h2[(size_t)(row + 8) * HID + col] =
                __floats2half2_rn(c[nt][2], c[nt][3]);
    }
    float ps[2] = {0.f, 0.f}, pd[2] = {0.f, 0.f};
#pragma unroll
    for (int nt = 0; nt < 4; nt++) {
        int colg = n_base + nt * 8 + kp;
        float sa0 = as2[colg], sa1 = as2[colg + 1];
        float da0 = ad2[colg], da1 = ad2[colg + 1];
        ps[0] += c[nt][0] * sa0 + c[nt][1] * sa1;
        pd[0] += c[nt][0] * da0 + c[nt][1] * da1;
        ps[1] += c[nt][2] * sa0 + c[nt][3] * sa1;
        pd[1] += c[nt][2] * da0 + c[nt][3] * da1;
    }
#pragma unroll
    for (int o = 1; o <= 2; o <<= 1) {
#pragma unroll
        for (int rh = 0; rh < 2; rh++) {
            ps[rh] += __shfl_xor_sync(0xFFFFFFFFu, ps[rh], o);
            pd[rh] += __shfl_xor_sync(0xFFFFFFFFu, pd[rh], o);
        }
    }
    if ((lane & 3) == 0) {
#pragma unroll
        for (int rh = 0; rh < 2; rh++) {
            int row = node0 + m_base + rh * 8 + r;
            if (row < NN) {
                atomicAdd(&g_asrc2[row], ps[rh]);
                atomicAdd(&g_adst2[row], pd[rh]);
            }
        }
    }
}

// layer-2 aggregation + final linear: warp per dst node, 4-wide unroll
__global__ __launch_bounds__(256) void k_agg2(const float* __restrict__ b2,
                                              const float* __restrict__ Wlin,
                                              const float* __restrict__ blin,
                                              float* __restrict__ out) {
    int w = (blockIdx.x * blockDim.x + threadIdx.x) >> 5;
    int lane = threadIdx.x & 31;
    if (w >= NN) return;
    unsigned beg = g_ptr[w], end = g_ptr[w + 1];
    float adw = g_adst2[w];
    float2 acc = make_float2(0.f, 0.f);
    float ds = 0.f;
    unsigned j = beg;
    for (; j + 4 <= end; j += 4) {
        int2 m0 = g_misc[j], m1 = g_misc[j + 1];
        int2 m2 = g_misc[j + 2], m3 = g_misc[j + 3];
        float a0 = g_asrc2[m0.x], a1 = g_asrc2[m1.x];
        float a2 = g_asrc2[m2.x], a3 = g_asrc2[m3.x];
        __half2 v0 = g_h2h[(size_t)m0.x * 32 + lane];
        __half2 v1 = g_h2h[(size_t)m1.x * 32 + lane];
        __half2 v2 = g_h2h[(size_t)m2.x * 32 + lane];
        __half2 v3 = g_h2h[(size_t)m3.x * 32 + lane];
        float al0 = __expf(lrelu(a0 + adw + __int_as_float(m0.y)));
        float al1 = __expf(lrelu(a1 + adw + __int_as_float(m1.y)));
        float al2 = __expf(lrelu(a2 + adw + __int_as_float(m2.y)));
        float al3 = __expf(lrelu(a3 + adw + __int_as_float(m3.y)));
        ds += (al0 + al1) + (al2 + al3);
        float2 f;
        f = __half22float2(v0); acc.x = fmaf(f.x, al0, acc.x); acc.y = fmaf(f.y, al0, acc.y);
        f = __half22float2(v1); acc.x = fmaf(f.x, al1, acc.x); acc.y = fmaf(f.y, al1, acc.y);
        f = __half22float2(v2); acc.x = fmaf(f.x, al2, acc.x); acc.y = fmaf(f.y, al2, acc.y);
        f = __half22float2(v3); acc.x = fmaf(f.x, al3, acc.x); acc.y = fmaf(f.y, al3, acc.y);
    }
    for (; j < end; j++) {
        int2 m0 = g_misc[j];
        float al0 = __expf(lrelu(g_asrc2[m0.x] + adw + __int_as_float(m0.y)));
        ds += al0;
        float2 f = __half22float2(g_h2h[(size_t)m0.x * 32 + lane]);
        acc.x = fmaf(f.x, al0, acc.x); acc.y = fmaf(f.y, al0, acc.y);
    }
    float inv = 1.f / (ds + 1e-16f);
    float v0 = fmaxf(acc.x * inv + b2[2 * lane], 0.f);
    float v1 = fmaxf(acc.y * inv + b2[2 * lane + 1], 0.f);
    float r = v0 * Wlin[2 * lane] + v1 * Wlin[2 * lane + 1];
#pragma unroll
    for (int o = 16; o >= 1; o >>= 1) r += __shfl_xor_sync(0xFFFFFFFFu, r, o);
    if (lane == 0) out[w] = r + blin[0];
}

// ---------------- launch ----------------
extern "C" void kernel_launch(void* const* d_in, const int* in_sizes, int n_in,
                              void* d_out, int out_size) {
    const float* x     = (const float*)d_in[0];
    const int*   ei    = (const int*)d_in[1];
    const float* eattr = (const float*)d_in[2];
    const float* W1    = (const float*)d_in[3];
    const float* We1   = (const float*)d_in[4];
    const float* as1   = (const float*)d_in[5];
    const float* ad1   = (const float*)d_in[6];
    const float* ae1   = (const float*)d_in[7];
    const float* b1    = (const float*)d_in[8];
    const float* W2    = (const float*)d_in[9];
    const float* We2   = (const float*)d_in[10];
    const float* as2   = (const float*)d_in[11];
    const float* ad2   = (const float*)d_in[12];
    const float* ae2   = (const float*)d_in[13];
    const float* b2    = (const float*)d_in[14];
    const float* Wlin  = (const float*)d_in[15];
    const float* blin  = (const float*)d_in[16];
    float* out = (float*)d_out;

    static cudaStream_t s2 = nullptr;
    static cudaEvent_t evFork = nullptr, evJoin = nullptr;
    static bool attr_done = false;
    if (!attr_done) {
        cudaFuncSetAttribute(k_gemm1, cudaFuncAttributeMaxDynamicSharedMemorySize, G1_SMEM);
        cudaFuncSetAttribute(k_gemm2, cudaFuncAttributeMaxDynamicSharedMemorySize, G2_SMEM);
        cudaStreamCreateWithFlags(&s2, cudaStreamNonBlocking);
        cudaEventCreateWithFlags(&evFork, cudaEventDisableTiming);
        cudaEventCreateWithFlags(&evJoin, cudaEventDisableTiming);
        attr_done = true;
    }

    // fork: CSR build + W2t/v-vectors on s2, concurrent with W1t+gemm1
    cudaEventRecord(evFork, 0);
    cudaStreamWaitEvent(s2, evFork, 0);
    k_initB<<<(HID * C1 + 255) / 256, 256, 0, s2>>>(We1, ae1, We2, ae2, W2);
    k_initdeg<<<(NN + 255) / 256, 256, 0, s2>>>();
    k_hist<<<NE / 256, 256, 0, s2>>>(ei);
    k_scan<<<1, 1024, 0, s2>>>();
    cudaEventRecord(evJoin, s2);

    k_initA<<<(NN + 255) / 256, 256>>>(W1);
    k_gemm1<<<dim3((NN + 63) / 64, 2), 256, G1_SMEM>>>(x, as1, ad1);

    // join: edge1 needs gemm1 results, CSR offsets, and v-vectors
    cudaStreamWaitEvent(0, evJoin, 0);
    k_edge1<<<(NE / 4 + 255) / 256, 256>>>(ei, eattr);
    k_agg1<<<(NN * 32 + 255) / 256, 256>>>(b1);
    k_gemm2<<<(NN + 63) / 64, 256, G2_SMEM>>>(as2, ad2);
    k_agg2<<<(NN * 32 + 255) / 256, 256>>>(b2, Wlin, blin, out);
}

// round 14
// speedup vs baseline: 1.8425x; 1.8425x over previous
#include <cuda_runtime.h>
#include <cuda_fp16.h>

#define NN 50000
#define NE 800000
#define IND 128
#define HID 64
#define HEADS 4
#define C1 256            // HEADS*HID
#define EDIM 16
#define NBLK_SCAN 196     // ceil(50000/256)

// ---------------- scratch (device globals) ----------------
__device__ uint4    g_h1h[NN * 32];         // [N,256] h1, fp16
__device__ __half2  g_out1h[NN * 128];      // [N,256] relu(agg1+b1), fp16
__device__ __half2  g_h2h[NN * 32];         // [N,64]  h2, fp16
__device__ __half   g_w1t[C1 * IND];        // W1^T fp16 [256 n][128 k]
__device__ __half   g_w2t[HID * C1];        // W2^T fp16 [64 n][256 k]
__device__ float4   g_scr1[NE];             // exp(logits) 4 heads, AT CSR POS
__device__ int2     g_misc[NE];             // (src, ae2-bits), AT CSR POS
__device__ float4   g_asrc1[NN], g_adst1[NN];
__device__ float    g_asrc2[NN], g_adst2[NN];
__device__ float    g_v1[EDIM * HEADS];
__device__ float    g_v2[EDIM];
__device__ unsigned g_deg[NN];
__device__ unsigned g_cnt[NN];
__device__ unsigned g_ptr[NN + 1];
__device__ unsigned g_bsum[256];

// ---------------- helpers ----------------
__device__ __forceinline__ float lrelu(float x) { return x > 0.f ? x : 0.2f * x; }
__device__ __forceinline__ float2 h2f(unsigned u) {
    return __half22float2(*reinterpret_cast<__half2*>(&u));
}
__device__ __forceinline__ void mma16816(float* c, const unsigned* a,
                                         unsigned b0, unsigned b1) {
    asm volatile(
        "mma.sync.aligned.m16n8k16.row.col.f32.f16.f16.f32 "
        "{%0,%1,%2,%3}, {%4,%5,%6,%7}, {%8,%9}, {%0,%1,%2,%3};"
        : "+f"(c[0]), "+f"(c[1]), "+f"(c[2]), "+f"(c[3])
        : "r"(a[0]), "r"(a[1]), "r"(a[2]), "r"(a[3]), "r"(b0), "r"(b1));
}
__device__ __forceinline__ void ldsm4(unsigned* r, unsigned addr) {
    asm volatile("ldmatrix.sync.aligned.m8n8.x4.shared.b16 {%0,%1,%2,%3}, [%4];"
                 : "=r"(r[0]), "=r"(r[1]), "=r"(r[2]), "=r"(r[3]) : "r"(addr));
}

// ---------------- kernels ----------------
// main stream: W1^T transpose + zero attention accumulators (gemm1's deps only)
__global__ __launch_bounds__(256) void k_initA(const float* __restrict__ W1) {
    int i = blockIdx.x * blockDim.x + threadIdx.x;
    if (i < NN) {
        float4 z = make_float4(0.f, 0.f, 0.f, 0.f);
        g_asrc1[i] = z; g_adst1[i] = z;
        g_asrc2[i] = 0.f; g_adst2[i] = 0.f;
    }
    if (i < C1 * IND) {
        int n = i >> 7, k = i & 127;
        g_w1t[i] = __float2half_rn(W1[k * C1 + n]);
    }
}

// stream B: zero degree counters
__global__ __launch_bounds__(256) void k_initdeg() {
    int i = blockIdx.x * blockDim.x + threadIdx.x;
    if (i < NN) g_deg[i] = 0u;
}

// stream B: W2^T + collapsed edge-attention vectors (warp per output)
__global__ __launch_bounds__(256) void k_initB(const float* __restrict__ We1,
                                               const float* __restrict__ ae1,
                                               const float* __restrict__ We2,
                                               const float* __restrict__ ae2,
                                               const float* __restrict__ W2) {
    int i = blockIdx.x * blockDim.x + threadIdx.x;
    if (i < HID * C1) {
        int n = i >> 8, k = i & 255;
        g_w2t[i] = __float2half_rn(W2[k * HID + n]);
    }
    int gw = i >> 5, lane = i & 31;
    if (gw < EDIM * HEADS) {
        int d = gw >> 2, h = gw & 3;
        float s = We1[d * C1 + h * HID + lane]        * ae1[h * HID + lane]
                + We1[d * C1 + h * HID + lane + 32]   * ae1[h * HID + lane + 32];
#pragma unroll
        for (int o = 16; o >= 1; o >>= 1) s += __shfl_xor_sync(0xFFFFFFFFu, s, o);
        if (lane == 0) g_v1[gw] = s;
    } else if (gw < EDIM * HEADS + EDIM) {
        int t = gw - EDIM * HEADS;
        float s = We2[t * HID + lane] * ae2[lane]
                + We2[t * HID + lane + 32] * ae2[lane + 32];
#pragma unroll
        for (int o = 16; o >= 1; o >>= 1) s += __shfl_xor_sync(0xFFFFFFFFu, s, o);
        if (lane == 0) g_v2[t] = s;
    }
}

__global__ __launch_bounds__(256) void k_hist(const int* __restrict__ ei) {
    int e = blockIdx.x * blockDim.x + threadIdx.x;
    if (e < NE) atomicAdd(&g_deg[ei[NE + e]], 1u);
}

// coalesced 3-phase scan: per-block exclusive scan (1 elem/thread)
__global__ __launch_bounds__(256) void k_scan1() {
    __shared__ unsigned wsum[8];
    int t = threadIdx.x;
    int i = blockIdx.x * 256 + t;
    unsigned v = (i < NN) ? g_deg[i] : 0u;
    unsigned lane = t & 31, wid = t >> 5;
    unsigned incl = v;
#pragma unroll
    for (int o = 1; o < 32; o <<= 1) {
        unsigned u = __shfl_up_sync(0xFFFFFFFFu, incl, o);
        if (lane >= (unsigned)o) incl += u;
    }
    if (lane == 31) wsum[wid] = incl;
    __syncthreads();
    if (t < 8) {
        unsigned w = wsum[t];
        unsigned inc = w;
#pragma unroll
        for (int o = 1; o < 8; o <<= 1) {
            unsigned u = __shfl_up_sync(0xFFu, inc, o);
            if (t >= o) inc += u;
        }
        wsum[t] = inc - w;                      // exclusive warp offset
        if (t == 7) g_bsum[blockIdx.x] = inc;   // block total
    }
    __syncthreads();
    if (i < NN) g_ptr[i] = incl - v + wsum[wid];
}

// exclusive scan of the 196 block sums (one block)
__global__ void k_scan2() {
    __shared__ unsigned wsum[8];
    int t = threadIdx.x;
    unsigned v = (t < NBLK_SCAN) ? g_bsum[t] : 0u;
    unsigned lane = t & 31, wid = t >> 5;
    unsigned incl = v;
#pragma unroll
    for (int o = 1; o < 32; o <<= 1) {
        unsigned u = __shfl_up_sync(0xFFFFFFFFu, incl, o);
        if (lane >= (unsigned)o) incl += u;
    }
    if (lane == 31) wsum[wid] = incl;
    __syncthreads();
    if (t < 8) {
        unsigned w = wsum[t];
        unsigned inc = w;
#pragma unroll
        for (int o = 1; o < 8; o <<= 1) {
            unsigned u = __shfl_up_sync(0xFFu, inc, o);
            if (t >= o) inc += u;
        }
        wsum[t] = inc - w;
    }
    __syncthreads();
    if (t < NBLK_SCAN) g_bsum[t] = incl - v + wsum[wid];
}

// add block offsets, finalize g_ptr and seed g_cnt
__global__ __launch_bounds__(256) void k_scan3() {
    int i = blockIdx.x * blockDim.x + threadIdx.x;
    if (i < NN) {
        unsigned p = g_ptr[i] + g_bsum[i >> 8];
        g_ptr[i] = p;
        g_cnt[i] = p;
    }
    if (i == NN) g_ptr[NN] = NE;
}

// ---- h1 = x @ W1 via HMMA+LDSM, att1 dots fused in epilogue ----
#define XS1_STRIDE 136
#define WS1_STRIDE 136
#define G1_SMEM ((64 * XS1_STRIDE + 128 * WS1_STRIDE) * 2)

__global__ __launch_bounds__(256) void k_gemm1(const float* __restrict__ x,
                                               const float* __restrict__ as1,
                                               const float* __restrict__ ad1) {
    extern __shared__ __half sm1[];
    __half* xs = sm1;                     // [64 m][136 k]
    __half* ws = sm1 + 64 * XS1_STRIDE;   // [128 n][136 k]
    int t = threadIdx.x;
    int node0 = blockIdx.x * 64;
    int ncol0 = blockIdx.y * 128;
#pragma unroll
    for (int i = 0; i < 8; i++) {
        int j = i * 256 + t;
        int m = j >> 5, kq = j & 31;
        float4 v = make_float4(0.f, 0.f, 0.f, 0.f);
        if (node0 + m < NN) v = ((const float4*)x)[(size_t)(node0 + m) * 32 + kq];
        *(__half2*)&xs[m * XS1_STRIDE + kq * 4]     = __floats2half2_rn(v.x, v.y);
        *(__half2*)&xs[m * XS1_STRIDE + kq * 4 + 2] = __floats2half2_rn(v.z, v.w);
    }
#pragma unroll
    for (int i = 0; i < 8; i++) {
        int j = i * 256 + t;
        int n = j >> 4, q = j & 15;
        uint4 v = ((const uint4*)(g_w1t + (size_t)(ncol0 + n) * IND))[q];
        *(uint4*)&ws[n * WS1_STRIDE + q * 8] = v;
    }
    __syncthreads();
    int warp = t >> 5, lane = t & 31;
    int wm = warp & 1, wn = warp >> 1;
    int m_base = wm * 32, n_base = wn * 32;
    unsigned xs_sa = (unsigned)__cvta_generic_to_shared(xs);
    unsigned ws_sa = (unsigned)__cvta_generic_to_shared(ws);
    unsigned aA = xs_sa + ((m_base + ((lane >> 3) & 1) * 8 + (lane & 7)) * XS1_STRIDE
                           + (lane >> 4) * 8) * 2;
    unsigned aB = ws_sa + ((n_base + (lane >> 4) * 8 + (lane & 7)) * WS1_STRIDE
                           + ((lane >> 3) & 1) * 8) * 2;
    float c[2][4][4];
#pragma unroll
    for (int i = 0; i < 2; i++)
#pragma unroll
        for (int j = 0; j < 4; j++)
#pragma unroll
            for (int q = 0; q < 4; q++) c[i][j][q] = 0.f;
#pragma unroll
    for (int k0 = 0; k0 < IND; k0 += 16) {
        unsigned a0[4], a1[4], b0[4], b1[4];
        ldsm4(a0, aA + k0 * 2);
        ldsm4(a1, aA + (16 * XS1_STRIDE + k0) * 2);
        ldsm4(b0, aB + k0 * 2);
        ldsm4(b1, aB + (16 * WS1_STRIDE + k0) * 2);
        mma16816(c[0][0], a0, b0[0], b0[1]);
        mma16816(c[0][1], a0, b0[2], b0[3]);
        mma16816(c[0][2], a0, b1[0], b1[1]);
        mma16816(c[0][3], a0, b1[2], b1[3]);
        mma16816(c[1][0], a1, b0[0], b0[1]);
        mma16816(c[1][1], a1, b0[2], b0[3]);
        mma16816(c[1][2], a1, b1[0], b1[1]);
        mma16816(c[1][3], a1, b1[2], b1[3]);
    }
    int r = lane >> 2, kp = (lane & 3) * 2;
    __half* h1 = (__half*)g_h1h;
#pragma unroll
    for (int mt = 0; mt < 2; mt++) {
#pragma unroll
        for (int nt = 0; nt < 4; nt++) {
            int row = node0 + m_base + mt * 16 + r;
            int col = ncol0 + n_base + nt * 8 + kp;
            if (row < NN)
                *(__half2*)&h1[(size_t)row * C1 + col] =
                    __floats2half2_rn(c[mt][nt][0], c[mt][nt][1]);
            if (row + 8 < NN)
                *(__half2*)&h1[(size_t)(row + 8) * C1 + col] =
                    __floats2half2_rn(c[mt][nt][2], c[mt][nt][3]);
        }
    }
    // fused attention dots: partial over this warp's 32 cols, quad-reduce, REDG
    float ps[2][2] = {{0.f, 0.f}, {0.f, 0.f}};
    float pd[2][2] = {{0.f, 0.f}, {0.f, 0.f}};
#pragma unroll
    for (int nt = 0; nt < 4; nt++) {
        int colg = ncol0 + n_base + nt * 8 + kp;
        float sa0 = as1[colg], sa1 = as1[colg + 1];
        float da0 = ad1[colg], da1 = ad1[colg + 1];
#pragma unroll
        for (int mt = 0; mt < 2; mt++) {
            ps[mt][0] += c[mt][nt][0] * sa0 + c[mt][nt][1] * sa1;
            pd[mt][0] += c[mt][nt][0] * da0 + c[mt][nt][1] * da1;
            ps[mt][1] += c[mt][nt][2] * sa0 + c[mt][nt][3] * sa1;
            pd[mt][1] += c[mt][nt][2] * da0 + c[mt][nt][3] * da1;
        }
    }
#pragma unroll
    for (int o = 1; o <= 2; o <<= 1) {
#pragma unroll
        for (int mt = 0; mt < 2; mt++)
#pragma unroll
            for (int rh = 0; rh < 2; rh++) {
                ps[mt][rh] += __shfl_xor_sync(0xFFFFFFFFu, ps[mt][rh], o);
                pd[mt][rh] += __shfl_xor_sync(0xFFFFFFFFu, pd[mt][rh], o);
            }
    }
    if ((lane & 3) == 0) {
        int head = (ncol0 + n_base) >> 6;
        float* s1f = (float*)g_asrc1;
        float* d1f = (float*)g_adst1;
#pragma unroll
        for (int mt = 0; mt < 2; mt++)
#pragma unroll
            for (int rh = 0; rh < 2; rh++) {
                int row = node0 + m_base + mt * 16 + rh * 8 + r;
                if (row < NN) {
                    atomicAdd(&s1f[row * 4 + head], ps[mt][rh]);
                    atomicAdd(&d1f[row * 4 + head], pd[mt][rh]);
                }
            }
    }
}

// per-edge logits + CSR scatter fused; 4 edges/thread for MLP
__global__ __launch_bounds__(256) void k_edge1(const int* __restrict__ ei,
                                               const float* __restrict__ eattr) {
    __shared__ float v1s[EDIM * HEADS];
    __shared__ float v2s[EDIM];
    if (threadIdx.x < EDIM * HEADS) v1s[threadIdx.x] = g_v1[threadIdx.x];
    if (threadIdx.x < EDIM)         v2s[threadIdx.x] = g_v2[threadIdx.x];
    __syncthreads();
    int base = blockIdx.x * blockDim.x + threadIdx.x;
    if (base >= NE / 4) return;
    int eidx[4] = {base, base + NE / 4, base + NE / 2, base + 3 * (NE / 4)};
    int s[4], d[4];
    float4 av[4], dv[4];
#pragma unroll
    for (int u = 0; u < 4; u++) {
        s[u] = ei[eidx[u]];
        d[u] = ei[NE + eidx[u]];
    }
#pragma unroll
    for (int u = 0; u < 4; u++) {
        av[u] = g_asrc1[s[u]];
        dv[u] = g_adst1[d[u]];
    }
#pragma unroll
    for (int u = 0; u < 4; u++) {
        const float4* ea = (const float4*)(eattr + (size_t)eidx[u] * EDIM);
        float ae[4] = {0.f, 0.f, 0.f, 0.f};
        float aev2 = 0.f;
#pragma unroll
        for (int j = 0; j < 4; j++) {
            float4 v = ea[j];
            float vals[4] = {v.x, v.y, v.z, v.w};
#pragma unroll
            for (int m = 0; m < 4; m++) {
                int dd = j * 4 + m;
                float ev = vals[m];
#pragma unroll
                for (int h = 0; h < 4; h++) ae[h] = fmaf(ev, v1s[dd * 4 + h], ae[h]);
                aev2 = fmaf(ev, v2s[dd], aev2);
            }
        }
        float4 ex;
        ex.x = __expf(lrelu(av[u].x + dv[u].x + ae[0]));
        ex.y = __expf(lrelu(av[u].y + dv[u].y + ae[1]));
        ex.z = __expf(lrelu(av[u].z + dv[u].z + ae[2]));
        ex.w = __expf(lrelu(av[u].w + dv[u].w + ae[3]));
        unsigned pos = atomicAdd(&g_cnt[d[u]], 1u);
        g_scr1[pos] = ex;
        g_misc[pos] = make_int2(s[u], __float_as_int(aev2));
    }
}

// layer-1 aggregation: warp per dst node, 4-wide unroll; bias+relu epilogue
__global__ __launch_bounds__(256) void k_agg1(const float* __restrict__ b1) {
    int w = (blockIdx.x * blockDim.x + threadIdx.x) >> 5;
    int lane = threadIdx.x & 31;
    if (w >= NN) return;
    unsigned beg = g_ptr[w], end = g_ptr[w + 1];
    int h = lane >> 3;
    const float* scr = (const float*)g_scr1;
    float a[8] = {0.f, 0.f, 0.f, 0.f, 0.f, 0.f, 0.f, 0.f};
    float ds = 0.f;
    unsigned j = beg;
    for (; j + 4 <= end; j += 4) {
        int s0 = g_misc[j].x, s1 = g_misc[j + 1].x;
        int s2 = g_misc[j + 2].x, s3 = g_misc[j + 3].x;
        float x0 = scr[(size_t)j * 4 + h];
        float x1 = scr[(size_t)(j + 1) * 4 + h];
        float x2 = scr[(size_t)(j + 2) * 4 + h];
        float x3 = scr[(size_t)(j + 3) * 4 + h];
        uint4 v0 = g_h1h[(size_t)s0 * 32 + lane];
        uint4 v1 = g_h1h[(size_t)s1 * 32 + lane];
        uint4 v2 = g_h1h[(size_t)s2 * 32 + lane];
        uint4 v3 = g_h1h[(size_t)s3 * 32 + lane];
        ds += (x0 + x1) + (x2 + x3);
        float2 f;
        f = h2f(v0.x); a[0] = fmaf(f.x, x0, a[0]); a[1] = fmaf(f.y, x0, a[1]);
        f = h2f(v0.y); a[2] = fmaf(f.x, x0, a[2]); a[3] = fmaf(f.y, x0, a[3]);
        f = h2f(v0.z); a[4] = fmaf(f.x, x0, a[4]); a[5] = fmaf(f.y, x0, a[5]);
        f = h2f(v0.w); a[6] = fmaf(f.x, x0, a[6]); a[7] = fmaf(f.y, x0, a[7]);
        f = h2f(v1.x); a[0] = fmaf(f.x, x1, a[0]); a[1] = fmaf(f.y, x1, a[1]);
        f = h2f(v1.y); a[2] = fmaf(f.x, x1, a[2]); a[3] = fmaf(f.y, x1, a[3]);
        f = h2f(v1.z); a[4] = fmaf(f.x, x1, a[4]); a[5] = fmaf(f.y, x1, a[5]);
        f = h2f(v1.w); a[6] = fmaf(f.x, x1, a[6]); a[7] = fmaf(f.y, x1, a[7]);
        f = h2f(v2.x); a[0] = fmaf(f.x, x2, a[0]); a[1] = fmaf(f.y, x2, a[1]);
        f = h2f(v2.y); a[2] = fmaf(f.x, x2, a[2]); a[3] = fmaf(f.y, x2, a[3]);
        f = h2f(v2.z); a[4] = fmaf(f.x, x2, a[4]); a[5] = fmaf(f.y, x2, a[5]);
        f = h2f(v2.w); a[6] = fmaf(f.x, x2, a[6]); a[7] = fmaf(f.y, x2, a[7]);
        f = h2f(v3.x); a[0] = fmaf(f.x, x3, a[0]); a[1] = fmaf(f.y, x3, a[1]);
        f = h2f(v3.y); a[2] = fmaf(f.x, x3, a[2]); a[3] = fmaf(f.y, x3, a[3]);
        f = h2f(v3.z); a[4] = fmaf(f.x, x3, a[4]); a[5] = fmaf(f.y, x3, a[5]);
        f = h2f(v3.w); a[6] = fmaf(f.x, x3, a[6]); a[7] = fmaf(f.y, x3, a[7]);
    }
    for (; j < end; j++) {
        int s0 = g_misc[j].x;
        float x0 = scr[(size_t)j * 4 + h];
        uint4 v0 = g_h1h[(size_t)s0 * 32 + lane];
        ds += x0;
        float2 f;
        f = h2f(v0.x); a[0] = fmaf(f.x, x0, a[0]); a[1] = fmaf(f.y, x0, a[1]);
        f = h2f(v0.y); a[2] = fmaf(f.x, x0, a[2]); a[3] = fmaf(f.y, x0, a[3]);
        f = h2f(v0.z); a[4] = fmaf(f.x, x0, a[4]); a[5] = fmaf(f.y, x0, a[5]);
        f = h2f(v0.w); a[6] = fmaf(f.x, x0, a[6]); a[7] = fmaf(f.y, x0, a[7]);
    }
    float inv = 1.f / (ds + 1e-16f);
    float4 b0 = ((const float4*)b1)[2 * lane];
    float4 b1v = ((const float4*)b1)[2 * lane + 1];
    __half2 r0 = __floats2half2_rn(fmaxf(a[0] * inv + b0.x, 0.f),
                                   fmaxf(a[1] * inv + b0.y, 0.f));
    __half2 r1 = __floats2half2_rn(fmaxf(a[2] * inv + b0.z, 0.f),
                                   fmaxf(a[3] * inv + b0.w, 0.f));
    __half2 r2 = __floats2half2_rn(fmaxf(a[4] * inv + b1v.x, 0.f),
                                   fmaxf(a[5] * inv + b1v.y, 0.f));
    __half2 r3 = __floats2half2_rn(fmaxf(a[6] * inv + b1v.z, 0.f),
                                   fmaxf(a[7] * inv + b1v.w, 0.f));
    uint4 pk;
    pk.x = *(unsigned*)&r0; pk.y = *(unsigned*)&r1;
    pk.z = *(unsigned*)&r2; pk.w = *(unsigned*)&r3;
    *reinterpret_cast<uint4*>(&g_out1h[(size_t)w * 128 + lane * 4]) = pk;
}

// ---- h2 = out1 @ W2 via HMMA+LDSM, att2 dots fused in epilogue ----
#define XS2_STRIDE 264
#define WS2_STRIDE 264
#define G2_SMEM ((64 * XS2_STRIDE + 64 * WS2_STRIDE) * 2)

__global__ __launch_bounds__(256) void k_gemm2(const float* __restrict__ as2,
                                               const float* __restrict__ ad2) {
    extern __shared__ __half sm2[];
    __half* xs = sm2;                     // [64 m][264 k]
    __half* ws = sm2 + 64 * XS2_STRIDE;   // [64 n][264 k]
    int t = threadIdx.x;
    int node0 = blockIdx.x * 64;
#pragma unroll
    for (int i = 0; i < 8; i++) {
        int j = i * 256 + t;
        int m = j >> 5, q = j & 31;
        uint4 v = make_uint4(0u, 0u, 0u, 0u);
        if (node0 + m < NN)
            v = ((const uint4*)g_out1h)[(size_t)(node0 + m) * 32 + q];
        *(uint4*)&xs[m * XS2_STRIDE + q * 8] = v;
    }
#pragma unroll
    for (int i = 0; i < 8; i++) {
        int j = i * 256 + t;
        int n = j >> 5, q = j & 31;
        uint4 v = ((const uint4*)(g_w2t + (size_t)n * C1))[q];
        *(uint4*)&ws[n * WS2_STRIDE + q * 8] = v;
    }
    __syncthreads();
    int warp = t >> 5, lane = t & 31;
    int wm = warp & 3, wn = warp >> 2;
    int m_base = wm * 16, n_base = wn * 32;
    unsigned xs_sa = (unsigned)__cvta_generic_to_shared(xs);
    unsigned ws_sa = (unsigned)__cvta_generic_to_shared(ws);
    unsigned aA = xs_sa + ((m_base + ((lane >> 3) & 1) * 8 + (lane & 7)) * XS2_STRIDE
                           + (lane >> 4) * 8) * 2;
    unsigned aB = ws_sa + ((n_base + (lane >> 4) * 8 + (lane & 7)) * WS2_STRIDE
                           + ((lane >> 3) & 1) * 8) * 2;
    float c[4][4];
#pragma unroll
    for (int j = 0; j < 4; j++)
#pragma unroll
        for (int q = 0; q < 4; q++) c[j][q] = 0.f;
#pragma unroll
    for (int k0 = 0; k0 < C1; k0 += 16) {
        unsigned a[4], b0[4], b1[4];
        ldsm4(a, aA + k0 * 2);
        ldsm4(b0, aB + k0 * 2);
        ldsm4(b1, aB + (16 * WS2_STRIDE + k0) * 2);
        mma16816(c[0], a, b0[0], b0[1]);
        mma16816(c[1], a, b0[2], b0[3]);
        mma16816(c[2], a, b1[0], b1[1]);
        mma16816(c[3], a, b1[2], b1[3]);
    }
    int r = lane >> 2, kp = (lane & 3) * 2;
    __half* h2 = (__half*)g_h2h;
#pragma unroll
    for (int nt = 0; nt < 4; nt++) {
        int row = node0 + m_base + r;
        int col = n_base + nt * 8 + kp;
        if (row < NN)
            *(__half2*)&h2[(size_t)row * HID + col] =
                __floats2half2_rn(c[nt][0], c[nt][1]);
        if (row + 8 < NN)
            *(__half2*)&h2[(size_t)(row + 8) * HID + col] =
                __floats2half2_rn(c[nt][2], c[nt][3]);
    }
    float ps[2] = {0.f, 0.f}, pd[2] = {0.f, 0.f};
#pragma unroll
    for (int nt = 0; nt < 4; nt++) {
        int colg = n_base + nt * 8 + kp;
        float sa0 = as2[colg], sa1 = as2[colg + 1];
        float da0 = ad2[colg], da1 = ad2[colg + 1];
        ps[0] += c[nt][0] * sa0 + c[nt][1] * sa1;
        pd[0] += c[nt][0] * da0 + c[nt][1] * da1;
        ps[1] += c[nt][2] * sa0 + c[nt][3] * sa1;
        pd[1] += c[nt][2] * da0 + c[nt][3] * da1;
    }
#pragma unroll
    for (int o = 1; o <= 2; o <<= 1) {
#pragma unroll
        for (int rh = 0; rh < 2; rh++) {
            ps[rh] += __shfl_xor_sync(0xFFFFFFFFu, ps[rh], o);
            pd[rh] += __shfl_xor_sync(0xFFFFFFFFu, pd[rh], o);
        }
    }
    if ((lane & 3) == 0) {
#pragma unroll
        for (int rh = 0; rh < 2; rh++) {
            int row = node0 + m_base + rh * 8 + r;
            if (row < NN) {
                atomicAdd(&g_asrc2[row], ps[rh]);
                atomicAdd(&g_adst2[row], pd[rh]);
            }
        }
    }
}

// layer-2 aggregation + final linear: warp per dst node, 4-wide unroll
__global__ __launch_bounds__(256) void k_agg2(const float* __restrict__ b2,
                                              const float* __restrict__ Wlin,
                                              const float* __restrict__ blin,
                                              float* __restrict__ out) {
    int w = (blockIdx.x * blockDim.x + threadIdx.x) >> 5;
    int lane = threadIdx.x & 31;
    if (w >= NN) return;
    unsigned beg = g_ptr[w], end = g_ptr[w + 1];
    float adw = g_adst2[w];
    float2 acc = make_float2(0.f, 0.f);
    float ds = 0.f;
    unsigned j = beg;
    for (; j + 4 <= end; j += 4) {
        int2 m0 = g_misc[j], m1 = g_misc[j + 1];
        int2 m2 = g_misc[j + 2], m3 = g_misc[j + 3];
        float a0 = g_asrc2[m0.x], a1 = g_asrc2[m1.x];
        float a2 = g_asrc2[m2.x], a3 = g_asrc2[m3.x];
        __half2 v0 = g_h2h[(size_t)m0.x * 32 + lane];
        __half2 v1 = g_h2h[(size_t)m1.x * 32 + lane];
        __half2 v2 = g_h2h[(size_t)m2.x * 32 + lane];
        __half2 v3 = g_h2h[(size_t)m3.x * 32 + lane];
        float al0 = __expf(lrelu(a0 + adw + __int_as_float(m0.y)));
        float al1 = __expf(lrelu(a1 + adw + __int_as_float(m1.y)));
        float al2 = __expf(lrelu(a2 + adw + __int_as_float(m2.y)));
        float al3 = __expf(lrelu(a3 + adw + __int_as_float(m3.y)));
        ds += (al0 + al1) + (al2 + al3);
        float2 f;
        f = __half22float2(v0); acc.x = fmaf(f.x, al0, acc.x); acc.y = fmaf(f.y, al0, acc.y);
        f = __half22float2(v1); acc.x = fmaf(f.x, al1, acc.x); acc.y = fmaf(f.y, al1, acc.y);
        f = __half22float2(v2); acc.x = fmaf(f.x, al2, acc.x); acc.y = fmaf(f.y, al2, acc.y);
        f = __half22float2(v3); acc.x = fmaf(f.x, al3, acc.x); acc.y = fmaf(f.y, al3, acc.y);
    }
    for (; j < end; j++) {
        int2 m0 = g_misc[j];
        float al0 = __expf(lrelu(g_asrc2[m0.x] + adw + __int_as_float(m0.y)));
        ds += al0;
        float2 f = __half22float2(g_h2h[(size_t)m0.x * 32 + lane]);
        acc.x = fmaf(f.x, al0, acc.x); acc.y = fmaf(f.y, al0, acc.y);
    }
    float inv = 1.f / (ds + 1e-16f);
    float v0 = fmaxf(acc.x * inv + b2[2 * lane], 0.f);
    float v1 = fmaxf(acc.y * inv + b2[2 * lane + 1], 0.f);
    float r = v0 * Wlin[2 * lane] + v1 * Wlin[2 * lane + 1];
#pragma unroll
    for (int o = 16; o >= 1; o >>= 1) r += __shfl_xor_sync(0xFFFFFFFFu, r, o);
    if (lane == 0) out[w] = r + blin[0];
}

// ---------------- launch ----------------
extern "C" void kernel_launch(void* const* d_in, const int* in_sizes, int n_in,
                              void* d_out, int out_size) {
    const float* x     = (const float*)d_in[0];
    const int*   ei    = (const int*)d_in[1];
    const float* eattr = (const float*)d_in[2];
    const float* W1    = (const float*)d_in[3];
    const float* We1   = (const float*)d_in[4];
    const float* as1   = (const float*)d_in[5];
    const float* ad1   = (const float*)d_in[6];
    const float* ae1   = (const float*)d_in[7];
    const float* b1    = (const float*)d_in[8];
    const float* W2    = (const float*)d_in[9];
    const float* We2   = (const float*)d_in[10];
    const float* as2   = (const float*)d_in[11];
    const float* ad2   = (const float*)d_in[12];
    const float* ae2   = (const float*)d_in[13];
    const float* b2    = (const float*)d_in[14];
    const float* Wlin  = (const float*)d_in[15];
    const float* blin  = (const float*)d_in[16];
    float* out = (float*)d_out;

    static cudaStream_t s2 = nullptr;
    static cudaEvent_t evFork = nullptr, evJoin = nullptr;
    static bool attr_done = false;
    if (!attr_done) {
        cudaFuncSetAttribute(k_gemm1, cudaFuncAttributeMaxDynamicSharedMemorySize, G1_SMEM);
        cudaFuncSetAttribute(k_gemm2, cudaFuncAttributeMaxDynamicSharedMemorySize, G2_SMEM);
        cudaStreamCreateWithFlags(&s2, cudaStreamNonBlocking);
        cudaEventCreateWithFlags(&evFork, cudaEventDisableTiming);
        cudaEventCreateWithFlags(&evJoin, cudaEventDisableTiming);
        attr_done = true;
    }

    // fork: CSR build + W2t/v-vectors on s2, concurrent with W1t+gemm1
    cudaEventRecord(evFork, 0);
    cudaStreamWaitEvent(s2, evFork, 0);
    k_initdeg<<<(NN + 255) / 256, 256, 0, s2>>>();
    k_hist<<<NE / 256, 256, 0, s2>>>(ei);
    k_scan1<<<NBLK_SCAN, 256, 0, s2>>>();
    k_scan2<<<1, 256, 0, s2>>>();
    k_scan3<<<(NN + 256) / 256, 256, 0, s2>>>();
    k_initB<<<(HID * C1 + 255) / 256, 256, 0, s2>>>(We1, ae1, We2, ae2, W2);
    cudaEventRecord(evJoin, s2);

    k_initA<<<(NN + 255) / 256, 256>>>(W1);
    k_gemm1<<<dim3((NN + 63) / 64, 2), 256, G1_SMEM>>>(x, as1, ad1);

    // join: edge1 needs gemm1 results, CSR offsets, and v-vectors
    cudaStreamWaitEvent(0, evJoin, 0);
    k_edge1<<<(NE / 4 + 255) / 256, 256>>>(ei, eattr);
    k_agg1<<<(NN * 32 + 255) / 256, 256>>>(b1);
    k_gemm2<<<(NN + 63) / 64, 256, G2_SMEM>>>(as2, ad2);
    k_agg2<<<(NN * 32 + 255) / 256, 256>>>(b2, Wlin, blin, out);
}